// round 3
// baseline (speedup 1.0000x reference)
#include <cuda_runtime.h>

// ---------------- scratch (device globals; no runtime allocation) -------------
__device__ float g_doff[2 * 144 * 256 * 256];
__device__ float g_aligned[2 * 64 * 256 * 256];
__device__ float g_x1[2 * 64 * 256 * 256];

static constexpr int Hc = 256;
static constexpr int Wc = 256;
static constexpr int HWc = Hc * Wc;

static constexpr int TS = 32;     // spatial tile (32x32 outputs)
static constexpr int HALO = 34;   // TS + 2
static constexpr int HPAD = 36;   // padded row stride
static constexpr int ICC = 8;     // input-channel chunk in smem
static constexpr int OCB = 8;     // output channels per block

// ---- packed f32x2 helpers (Blackwell FFMA2; ptxas never auto-fuses) ----------
__device__ __forceinline__ unsigned long long pack2(float lo, float hi) {
  unsigned long long r;
  asm("mov.b64 %0, {%1, %2};" : "=l"(r) : "f"(lo), "f"(hi));
  return r;
}
__device__ __forceinline__ void unpack2(unsigned long long v, float& lo, float& hi) {
  asm("mov.b64 {%0, %1}, %2;" : "=f"(lo), "=f"(hi) : "l"(v));
}
__device__ __forceinline__ unsigned long long fma2(unsigned long long a,
                                                   unsigned long long b,
                                                   unsigned long long c) {
  unsigned long long d;
  asm("fma.rn.f32x2 %0, %1, %2, %3;" : "=l"(d) : "l"(a), "l"(b), "l"(c));
  return d;
}

// ---------------- generic 3x3 SAME conv, NCHW, fp32 (FFMA2 core) --------------
// 256 threads = 32 rows x 8 col-groups; each thread computes a 1x4 strip of
// outputs for 8 output channels, as 2 packed f32x2 accumulators per channel.
template <int IC>
__global__ __launch_bounds__(256, 2) void conv3x3_tiled(
    const float* __restrict__ inA, const float* __restrict__ inB,
    const float* __restrict__ w,    // [OC][IC][3][3]
    const float* __restrict__ bias, // [OC]
    float* __restrict__ out,        // [B][OC][H][W]
    int OC, int do_relu, const float* __restrict__ addsrc) {
  __shared__ float s_in[ICC][HALO][HPAD];
  __shared__ float2 s_w2[ICC][9][OCB];  // weight duplicated as (w,w)

  const int tilesW = Wc / TS;
  const int tx0 = (blockIdx.x % tilesW) * TS;
  const int ty0 = (blockIdx.x / tilesW) * TS;
  const int oc0 = blockIdx.y * OCB;
  const int b = blockIdx.z;
  const int t = threadIdx.x;
  const int px = (t & 7) * 4;  // 1x4 strip
  const int py = t >> 3;       // 0..31

  unsigned long long acc[OCB][2];
#pragma unroll
  for (int o = 0; o < OCB; o++) { acc[o][0] = 0ull; acc[o][1] = 0ull; }

  for (int ic0 = 0; ic0 < IC; ic0 += ICC) {
    // ---- load input halo chunk (zero-padded; pad cols 34,35 dead) ----
    for (int i = t; i < ICC * HALO * HPAD; i += 256) {
      int ic = i / (HALO * HPAD);
      int r = i - ic * (HALO * HPAD);
      int yy = r / HPAD;
      int xx = r - yy * HPAD;
      int gy = ty0 + yy - 1;
      int gx = tx0 + xx - 1;
      float v = 0.f;
      if ((unsigned)gy < (unsigned)Hc && (unsigned)gx < (unsigned)Wc) {
        int icg = ic0 + ic;
        const float* src = inA;
        int icl = icg;
        if (IC == 128 && icg >= 64) { src = inB; icl = icg - 64; }
        v = src[(b * 64 + icl) * HWc + gy * Wc + gx];
      }
      (&s_in[0][0][0])[i] = v;
    }
    // ---- load weight chunk, transposed + duplicated: [ic][tap][o] = (w,w) ----
    for (int i = t; i < ICC * 9 * OCB; i += 256) {
      int ic = i / (9 * OCB);
      int r = i - ic * (9 * OCB);
      int k = r >> 3;
      int o = r & 7;
      float v = w[(oc0 + o) * IC * 9 + (ic0 + ic) * 9 + k];
      s_w2[ic][k][o] = make_float2(v, v);
    }
    __syncthreads();

#pragma unroll 1
    for (int ic = 0; ic < ICC; ic++) {
#pragma unroll
      for (int ky = 0; ky < 3; ky++) {
        const float* rowp = &s_in[ic][py + ky][px];
        float4 va = *(const float4*)rowp;        // cols px..px+3
        float2 vb = *(const float2*)(rowp + 4);  // cols px+4..px+5
        // sliding-window packed pairs for kx = 0,1,2
        unsigned long long in_lo[3], in_hi[3];
        in_lo[0] = pack2(va.x, va.y);
        in_hi[0] = pack2(va.z, va.w);
        in_lo[1] = pack2(va.y, va.z);
        in_hi[1] = pack2(va.w, vb.x);
        in_lo[2] = in_hi[0];                     // (va.z, va.w)
        in_hi[2] = pack2(vb.x, vb.y);
#pragma unroll
        for (int kx = 0; kx < 3; kx++) {
          const float2* wp = &s_w2[ic][ky * 3 + kx][0];
          // 4x LDS.128, each yields two duplicated weight pairs
          unsigned long long wpair[8];
#pragma unroll
          for (int q = 0; q < 4; q++) {
            float4 wv = *(const float4*)(wp + 2 * q);
            wpair[2 * q + 0] = pack2(wv.x, wv.y);  // (w,w) — compiler keeps as reg pair
            wpair[2 * q + 1] = pack2(wv.z, wv.w);
          }
#pragma unroll
          for (int o = 0; o < 8; o++) {
            acc[o][0] = fma2(in_lo[kx], wpair[o], acc[o][0]);
            acc[o][1] = fma2(in_hi[kx], wpair[o], acc[o][1]);
          }
        }
      }
    }
    __syncthreads();
  }

  // ---- epilogue: bias, relu, optional residual add; vectorized stores ----
  const int gy = ty0 + py;
  const int gx = tx0 + px;
#pragma unroll
  for (int o = 0; o < OCB; o++) {
    int oc = oc0 + o;
    float bv = bias[oc];
    float4 v;
    unpack2(acc[o][0], v.x, v.y);
    unpack2(acc[o][1], v.z, v.w);
    v.x += bv; v.y += bv; v.z += bv; v.w += bv;
    if (do_relu) {
      v.x = fmaxf(v.x, 0.f); v.y = fmaxf(v.y, 0.f);
      v.z = fmaxf(v.z, 0.f); v.w = fmaxf(v.w, 0.f);
    }
    int idx = (b * OC + oc) * HWc + gy * Wc + gx;
    if (addsrc) {
      float4 a4 = *(const float4*)&addsrc[idx];
      v.x += a4.x; v.y += a4.y; v.z += a4.z; v.w += a4.w;
    }
    *(float4*)&out[idx] = v;
  }
}

// ---------------- deformable conv (G=8, Cg=8, K=3) ---------------------------
__global__ __launch_bounds__(256) void deform_kernel(
    const float* __restrict__ ref,    // [B][64][H][W]
    const float* __restrict__ doff,   // [B][144][H][W]
    const float* __restrict__ w_def,  // [64][8][3][3]
    const float* __restrict__ b_def,  // [64]
    float* __restrict__ out) {        // [B][64][H][W]
  const int x = threadIdx.x;
  const int y = blockIdx.x;
  const int g = blockIdx.y;
  const int b = blockIdx.z;

  __shared__ float s_w[8][8][9];  // [o][i][k] for this group
  for (int i = threadIdx.x; i < 576; i += 256) {
    int o = i / 72;
    int r = i - o * 72;
    s_w[o][0][r] = w_def[(g * 8 + o) * 72 + r];
  }
  __syncthreads();

  const float* refg = ref + (b * 64 + g * 8) * HWc;
  const float* offg = doff + (b * 144 + g * 18) * HWc + y * Wc + x;

  float acc[8];
#pragma unroll
  for (int o = 0; o < 8; o++) acc[o] = 0.f;

#pragma unroll 1
  for (int k = 0; k < 9; k++) {
    float dy = offg[(2 * k) * HWc];
    float dx = offg[(2 * k + 1) * HWc];
    float pyf = dy + (float)(y + k / 3 - 1);
    float pxf = dx + (float)(x + k % 3 - 1);
    float fy = floorf(pyf);
    float fx = floorf(pxf);
    int y0 = (int)fy;
    int x0 = (int)fx;
    float ly = pyf - fy;
    float lx = pxf - fx;
    float w00 = (1.f - ly) * (1.f - lx);
    float w01 = (1.f - ly) * lx;
    float w10 = ly * (1.f - lx);
    float w11 = ly * lx;
    bool vy0 = (unsigned)y0 < (unsigned)Hc;
    bool vy1 = (unsigned)(y0 + 1) < (unsigned)Hc;
    bool vx0 = (unsigned)x0 < (unsigned)Wc;
    bool vx1 = (unsigned)(x0 + 1) < (unsigned)Wc;
    if (!(vy0 && vx0)) w00 = 0.f;
    if (!(vy0 && vx1)) w01 = 0.f;
    if (!(vy1 && vx0)) w10 = 0.f;
    if (!(vy1 && vx1)) w11 = 0.f;
    int cy0 = min(max(y0, 0), Hc - 1);
    int cy1 = min(max(y0 + 1, 0), Hc - 1);
    int cx0 = min(max(x0, 0), Wc - 1);
    int cx1 = min(max(x0 + 1, 0), Wc - 1);
    int i00 = cy0 * Wc + cx0;
    int i01 = cy0 * Wc + cx1;
    int i10 = cy1 * Wc + cx0;
    int i11 = cy1 * Wc + cx1;
#pragma unroll
    for (int c = 0; c < 8; c++) {
      const float* rp = refg + c * HWc;
      float s = w00 * rp[i00] + w01 * rp[i01] + w10 * rp[i10] + w11 * rp[i11];
#pragma unroll
      for (int o = 0; o < 8; o++) acc[o] = fmaf(s, s_w[o][c][k], acc[o]);
    }
  }

#pragma unroll
  for (int o = 0; o < 8; o++)
    out[(b * 64 + g * 8 + o) * HWc + y * Wc + x] = acc[o] + b_def[g * 8 + o];
}

// ---------------- launch ------------------------------------------------------
extern "C" void kernel_launch(void* const* d_in, const int* in_sizes, int n_in,
                              void* d_out, int out_size) {
  const float* offset = (const float*)d_in[0];
  const float* ref    = (const float*)d_in[1];
  const float* w_off  = (const float*)d_in[2];
  const float* b_off  = (const float*)d_in[3];
  const float* w_def  = (const float*)d_in[4];
  const float* b_def  = (const float*)d_in[5];
  const float* w_r1   = (const float*)d_in[6];
  const float* b_r1   = (const float*)d_in[7];
  const float* w_r2   = (const float*)d_in[8];
  const float* b_r2   = (const float*)d_in[9];
  float* out = (float*)d_out;

  float *p_doff, *p_aligned, *p_x1;
  cudaGetSymbolAddress((void**)&p_doff, g_doff);
  cudaGetSymbolAddress((void**)&p_aligned, g_aligned);
  cudaGetSymbolAddress((void**)&p_x1, g_x1);

  const int tiles = (Hc / TS) * (Wc / TS);  // 64

  // 1) deform_offsets = conv3x3(offset, w_off, b_off)   64 -> 144
  {
    dim3 grid(tiles, 144 / OCB, 2);
    conv3x3_tiled<64><<<grid, 256>>>(offset, nullptr, w_off, b_off, p_doff,
                                     144, 0, nullptr);
  }
  // 2) aligned_ref = deform_conv2d(ref, deform_offsets, w_def, b_def)
  {
    dim3 grid(Hc, 8, 2);
    deform_kernel<<<grid, 256>>>(ref, p_doff, w_def, b_def, p_aligned);
  }
  // 3) x1 = relu(conv3x3(concat(ref, aligned), w_r1, b_r1))  128 -> 64
  {
    dim3 grid(tiles, 64 / OCB, 2);
    conv3x3_tiled<128><<<grid, 256>>>(ref, p_aligned, w_r1, b_r1, p_x1,
                                      64, 1, nullptr);
  }
  // 4) out = relu(conv3x3(x1, w_r2, b_r2)) + aligned        64 -> 64
  {
    dim3 grid(tiles, 64 / OCB, 2);
    conv3x3_tiled<64><<<grid, 256>>>(p_x1, nullptr, w_r2, b_r2, out,
                                     64, 1, p_aligned);
  }
}

// round 7
// speedup vs baseline: 1.8810x; 1.8810x over previous
#include <cuda_runtime.h>
#include <cstdint>

__device__ float g_doff[2 * 144 * 256 * 256];
__device__ float g_aligned[2 * 64 * 256 * 256];
__device__ float g_x1[2 * 64 * 256 * 256];

static constexpr int Hc = 256, Wc = 256, HWc = Hc * Wc;

// smem (uint32 units): B raw stage 16ic x 3rows x 164 | A hi | A lo (64 x 148)
static constexpr int BST_U = 16 * 3 * 164;        // 7872
static constexpr int AST_U = 64 * 148;            // 9472
static constexpr int SMEM_U = BST_U + 2 * AST_U;  // 26816
static constexpr size_t SMEM_BYTES = (size_t)SMEM_U * 4;

__device__ __forceinline__ uint32_t f2tf(float f) {
  uint32_t r;
  asm("cvt.rna.tf32.f32 %0, %1;" : "=r"(r) : "f"(f));
  return r;
}
__device__ __forceinline__ void mma8(float* c, uint32_t a0, uint32_t a1,
                                     uint32_t a2, uint32_t a3, uint32_t b0,
                                     uint32_t b1) {
  asm volatile(
      "mma.sync.aligned.m16n8k8.row.col.f32.tf32.tf32.f32 "
      "{%0,%1,%2,%3}, {%4,%5,%6,%7}, {%8,%9}, {%0,%1,%2,%3};"
      : "+f"(c[0]), "+f"(c[1]), "+f"(c[2]), "+f"(c[3])
      : "r"(a0), "r"(a1), "r"(a2), "r"(a3), "r"(b0), "r"(b1));
}

// One CTA: 128-px x-strip of row y, 64 output channels (blockIdx.y block).
// GEMM D[64 oc][128 px] = W[oc][k=ic*9] * X[k][px], K chunked 144 (16 ic).
// 8 warps: warp tile 32m x 32n (2 m-frags x 4 n-frags of m16n8k8).
template <int NHALF>  // IC = NHALF*64
__global__ void __launch_bounds__(256, 2)
conv3x3_mma(const float* __restrict__ inA, const float* __restrict__ inB,
            const float* __restrict__ w, const float* __restrict__ bias,
            float* __restrict__ out, const float* __restrict__ addsrc,
            int OC_total, int do_relu) {
  extern __shared__ uint32_t smu[];
  uint32_t* Bst = smu;             // staged activations (tf32 bits)
  uint32_t* Ah = smu + BST_U;      // weights hi
  uint32_t* Al = Ah + AST_U;       // weights lo

  const int t = threadIdx.x, lane = t & 31, wid = t >> 5;
  const int gid = lane >> 2, tig = lane & 3;
  const int wm = wid & 1, wn = wid >> 1;

  const int bx = blockIdx.x;
  const int xt = bx & 1, y = (bx >> 1) & 255, b = bx >> 9;
  const int x0 = xt * 128;
  const int oc0 = blockIdx.y * 64;
  const int OCv = min(64, OC_total - oc0);
  const int Ktot = NHALF * 576;

  const int n_base = wn * 32 + gid;

  float acc[2][4][4];
#pragma unroll
  for (int f = 0; f < 2; f++)
#pragma unroll
    for (int j = 0; j < 4; j++)
#pragma unroll
      for (int e = 0; e < 4; e++) acc[f][j][e] = 0.f;

  for (int h = 0; h < NHALF; h++) {
    const float* src = (h == 0) ? inA : inB;
    for (int chunk = 0; chunk < 4; chunk++) {
      __syncthreads();  // previous chunk fully consumed
      // ---- stage activations: 16 ic x 3 rows x 160 px (stride 164) ----
      for (int i = t; i < 16 * 3 * 40; i += 256) {
        int ic = i / 120, r = i - ic * 120;
        int kyr = r / 40, q = r - kyr * 40;
        int gy = y + kyr - 1, gx0 = x0 - 16 + q * 4;
        float4 v = make_float4(0.f, 0.f, 0.f, 0.f);
        if ((unsigned)gy < 256u) {
          const float* sp =
              src + ((size_t)(b * 64 + chunk * 16 + ic)) * HWc + (size_t)gy * 256;
          if (gx0 >= 0 && gx0 <= 252) {
            v = *(const float4*)(sp + gx0);
          } else {
            float* pv = &v.x;
#pragma unroll
            for (int e = 0; e < 4; e++) {
              int gx = gx0 + e;
              if ((unsigned)gx < 256u) pv[e] = sp[gx];
            }
          }
        }
        uint4 u;
        u.x = f2tf(v.x); u.y = f2tf(v.y); u.z = f2tf(v.z); u.w = f2tf(v.w);
        *(uint4*)&Bst[(ic * 3 + kyr) * 164 + q * 4] = u;
      }
      // ---- stage weights hi/lo: 64 m x 144 k (stride 148) ----
      const int kofs = h * 576 + chunk * 144;
      for (int i = t; i < 64 * 36; i += 256) {
        int m = i / 36, q = (i - m * 36) * 4;
        float4 v = make_float4(0.f, 0.f, 0.f, 0.f);
        if (m < OCv)
          v = *(const float4*)(w + (size_t)(oc0 + m) * Ktot + kofs + q);
        uint4 hi, lo;
        float* pv = &v.x;
        uint32_t* ph = &hi.x;
        uint32_t* pl = &lo.x;
#pragma unroll
        for (int e = 0; e < 4; e++) {
          uint32_t hb = f2tf(pv[e]);
          ph[e] = hb;
          pl[e] = f2tf(pv[e] - __uint_as_float(hb));
        }
        *(uint4*)&Ah[m * 148 + q] = hi;
        *(uint4*)&Al[m * 148 + q] = lo;
      }
      __syncthreads();

      // ---- 18 k8 steps ----
#pragma unroll 1
      for (int ks = 0; ks < 18; ks++) {
        int kk0 = ks * 8 + tig;
        int kk1 = kk0 + 4;
        int ic0 = kk0 / 9, tap0 = kk0 - ic0 * 9;
        int ic1 = kk1 / 9, tap1 = kk1 - ic1 * 9;
        int rb0 = (ic0 * 3 + tap0 / 3) * 164 + (tap0 % 3) + 15 + n_base;
        int rb1 = (ic1 * 3 + tap1 / 3) * 164 + (tap1 % 3) + 15 + n_base;
        uint32_t b0[4], b1[4];
#pragma unroll
        for (int j = 0; j < 4; j++) {
          b0[j] = Bst[rb0 + j * 8];
          b1[j] = Bst[rb1 + j * 8];
        }
#pragma unroll
        for (int f = 0; f < 2; f++) {
          int arow = (wm * 32 + f * 16 + gid) * 148 + ks * 8;
          uint32_t a0 = Ah[arow + tig];
          uint32_t a1 = Ah[arow + 8 * 148 + tig];
          uint32_t a2 = Ah[arow + tig + 4];
          uint32_t a3 = Ah[arow + 8 * 148 + tig + 4];
#pragma unroll
          for (int j = 0; j < 4; j++) mma8(acc[f][j], a0, a1, a2, a3, b0[j], b1[j]);
          a0 = Al[arow + tig];
          a1 = Al[arow + 8 * 148 + tig];
          a2 = Al[arow + tig + 4];
          a3 = Al[arow + 8 * 148 + tig + 4];
#pragma unroll
          for (int j = 0; j < 4; j++) mma8(acc[f][j], a0, a1, a2, a3, b0[j], b1[j]);
        }
      }
    }
  }

  // ---- epilogue ----
#pragma unroll
  for (int f = 0; f < 2; f++) {
#pragma unroll
    for (int half = 0; half < 2; half++) {
      int m = wm * 32 + f * 16 + gid + half * 8;
      if (m >= OCv) continue;
      int oc = oc0 + m;
      float bv = bias[oc];
      size_t base =
          ((size_t)b * OC_total + oc) * HWc + (size_t)y * 256 + x0 + wn * 32 + tig * 2;
      float* op = out + base;
      const float* ap = addsrc ? addsrc + base : nullptr;
#pragma unroll
      for (int j = 0; j < 4; j++) {
        float v0 = acc[f][j][half * 2 + 0] + bv;
        float v1 = acc[f][j][half * 2 + 1] + bv;
        if (do_relu) { v0 = fmaxf(v0, 0.f); v1 = fmaxf(v1, 0.f); }
        if (ap) {
          float2 a2 = *(const float2*)(ap + j * 8);
          v0 += a2.x; v1 += a2.y;
        }
        *(float2*)(op + j * 8) = make_float2(v0, v1);
      }
    }
  }
}

// ---------------- deformable conv (G=8, Cg=8, K=3) ---------------------------
__global__ __launch_bounds__(256) void deform_kernel(
    const float* __restrict__ ref, const float* __restrict__ doff,
    const float* __restrict__ w_def, const float* __restrict__ b_def,
    float* __restrict__ out) {
  const int x = threadIdx.x, y = blockIdx.x, g = blockIdx.y, b = blockIdx.z;
  __shared__ float s_w[8][8][9];
  for (int i = threadIdx.x; i < 576; i += 256) {
    int o = i / 72, r = i - o * 72;
    s_w[o][0][r] = w_def[(g * 8 + o) * 72 + r];
  }
  __syncthreads();
  const float* refg = ref + (b * 64 + g * 8) * HWc;
  const float* offg = doff + (b * 144 + g * 18) * HWc + y * Wc + x;
  float acc[8];
#pragma unroll
  for (int o = 0; o < 8; o++) acc[o] = 0.f;
#pragma unroll 1
  for (int k = 0; k < 9; k++) {
    float dy = offg[(2 * k) * HWc];
    float dx = offg[(2 * k + 1) * HWc];
    float pyf = dy + (float)(y + k / 3 - 1);
    float pxf = dx + (float)(x + k % 3 - 1);
    float fy = floorf(pyf), fx = floorf(pxf);
    int y0 = (int)fy, x0 = (int)fx;
    float ly = pyf - fy, lx = pxf - fx;
    float w00 = (1.f - ly) * (1.f - lx), w01 = (1.f - ly) * lx;
    float w10 = ly * (1.f - lx), w11 = ly * lx;
    bool vy0 = (unsigned)y0 < 256u, vy1 = (unsigned)(y0 + 1) < 256u;
    bool vx0 = (unsigned)x0 < 256u, vx1 = (unsigned)(x0 + 1) < 256u;
    if (!(vy0 && vx0)) w00 = 0.f;
    if (!(vy0 && vx1)) w01 = 0.f;
    if (!(vy1 && vx0)) w10 = 0.f;
    if (!(vy1 && vx1)) w11 = 0.f;
    int cy0 = min(max(y0, 0), 255), cy1 = min(max(y0 + 1, 0), 255);
    int cx0 = min(max(x0, 0), 255), cx1 = min(max(x0 + 1, 0), 255);
    int i00 = cy0 * Wc + cx0, i01 = cy0 * Wc + cx1;
    int i10 = cy1 * Wc + cx0, i11 = cy1 * Wc + cx1;
#pragma unroll
    for (int cch = 0; cch < 8; cch++) {
      const float* rp = refg + cch * HWc;
      float s = w00 * rp[i00] + w01 * rp[i01] + w10 * rp[i10] + w11 * rp[i11];
#pragma unroll
      for (int o = 0; o < 8; o++) acc[o] = fmaf(s, s_w[o][cch][k], acc[o]);
    }
  }
#pragma unroll
  for (int o = 0; o < 8; o++)
    out[(b * 64 + g * 8 + o) * HWc + y * Wc + x] = acc[o] + b_def[g * 8 + o];
}

extern "C" void kernel_launch(void* const* d_in, const int* in_sizes, int n_in,
                              void* d_out, int out_size) {
  const float* offset = (const float*)d_in[0];
  const float* ref    = (const float*)d_in[1];
  const float* w_off  = (const float*)d_in[2];
  const float* b_off  = (const float*)d_in[3];
  const float* w_def  = (const float*)d_in[4];
  const float* b_def  = (const float*)d_in[5];
  const float* w_r1   = (const float*)d_in[6];
  const float* b_r1   = (const float*)d_in[7];
  const float* w_r2   = (const float*)d_in[8];
  const float* b_r2   = (const float*)d_in[9];
  float* out = (float*)d_out;

  float *p_doff, *p_aligned, *p_x1;
  cudaGetSymbolAddress((void**)&p_doff, g_doff);
  cudaGetSymbolAddress((void**)&p_aligned, g_aligned);
  cudaGetSymbolAddress((void**)&p_x1, g_x1);

  cudaFuncSetAttribute(conv3x3_mma<1>, cudaFuncAttributeMaxDynamicSharedMemorySize,
                       (int)SMEM_BYTES);
  cudaFuncSetAttribute(conv3x3_mma<2>, cudaFuncAttributeMaxDynamicSharedMemorySize,
                       (int)SMEM_BYTES);

  // 1) deform_offsets = conv3x3(offset)  64 -> 144 (3 oc-blocks of 64/64/16)
  conv3x3_mma<1><<<dim3(1024, 3), 256, SMEM_BYTES>>>(offset, nullptr, w_off, b_off,
                                                     p_doff, nullptr, 144, 0);
  // 2) deformable conv
  deform_kernel<<<dim3(256, 8, 2), 256>>>(ref, p_doff, w_def, b_def, p_aligned);
  // 3) x1 = relu(conv3x3(concat(ref, aligned)))  128 -> 64
  conv3x3_mma<2><<<dim3(1024, 1), 256, SMEM_BYTES>>>(ref, p_aligned, w_r1, b_r1,
                                                     p_x1, nullptr, 64, 1);
  // 4) out = relu(conv3x3(x1)) + aligned  64 -> 64
  conv3x3_mma<1><<<dim3(1024, 1), 256, SMEM_BYTES>>>(p_x1, nullptr, w_r2, b_r2,
                                                     out, p_aligned, 64, 1);
}

// round 8
// speedup vs baseline: 2.1648x; 1.1509x over previous
#include <cuda_runtime.h>
#include <cstdint>

__device__ float g_doff[2 * 144 * 256 * 256];
__device__ float g_aligned[2 * 64 * 256 * 256];
__device__ float g_x1[2 * 64 * 256 * 256];

static constexpr int Hc = 256, Wc = 256, HWc = Hc * Wc;

// smem (uint32 words):
//  Bst: 8 ic x 3 rows x 264 (tf32 bits; idx = gx+4, gx in [-1,256])
//  Ah/Al: 64 m x 84 (72 k in tap-major order k = tap*8+ic, +12 pad -> stride%32==20)
static constexpr int BSTR = 264;
static constexpr int BST_U = 8 * 3 * BSTR;   // 6336
static constexpr int ASTR = 84;
static constexpr int AST_U = 64 * ASTR;      // 5376
static constexpr int SMEM_U = BST_U + 2 * AST_U;  // 17088
static constexpr size_t SMEM_BYTES = (size_t)SMEM_U * 4;

__device__ __forceinline__ uint32_t f2tf(float f) {
  uint32_t r;
  asm("cvt.rna.tf32.f32 %0, %1;" : "=r"(r) : "f"(f));
  return r;
}
__device__ __forceinline__ void mma8(float* c, uint32_t a0, uint32_t a1,
                                     uint32_t a2, uint32_t a3, uint32_t b0,
                                     uint32_t b1) {
  asm volatile(
      "mma.sync.aligned.m16n8k8.row.col.f32.tf32.tf32.f32 "
      "{%0,%1,%2,%3}, {%4,%5,%6,%7}, {%8,%9}, {%0,%1,%2,%3};"
      : "+f"(c[0]), "+f"(c[1]), "+f"(c[2]), "+f"(c[3])
      : "r"(a0), "r"(a1), "r"(a2), "r"(a3), "r"(b0), "r"(b1));
}

// CTA: one full image row y (256 px) x 64 output channels.
// 8 warps: warp tile 32m x 64n. K chunked by 72 (8 ic x 9 taps, tap-major).
template <int NHALF>  // IC = NHALF*64
__global__ void __launch_bounds__(256, 2)
conv3x3_mma(const float* __restrict__ inA, const float* __restrict__ inB,
            const float* __restrict__ w, const float* __restrict__ bias,
            float* __restrict__ out, const float* __restrict__ addsrc,
            int OC_total, int do_relu) {
  extern __shared__ uint32_t smu[];
  uint32_t* Bst = smu;
  uint32_t* Ah = smu + BST_U;
  uint32_t* Al = Ah + AST_U;

  const int t = threadIdx.x, lane = t & 31, wid = t >> 5;
  const int gid = lane >> 2, tig = lane & 3;
  const int wm = wid & 1, wn = wid >> 1;  // wn 0..3 -> 64n slabs

  const int y = blockIdx.x & 255, b = blockIdx.x >> 8;
  const int oc0 = blockIdx.y * 64;
  const int OCv = min(64, OC_total - oc0);
  const int Ktot = NHALF * 576;

  // B address base: rows = ic(tig)*3 + ky, cols = px + kx + 3
  const int rB = tig * (3 * BSTR) + wn * 64 + gid;

  float acc[2][8][4];
#pragma unroll
  for (int f = 0; f < 2; f++)
#pragma unroll
    for (int j = 0; j < 8; j++)
#pragma unroll
      for (int e = 0; e < 4; e++) acc[f][j][e] = 0.f;

  for (int h = 0; h < NHALF; h++) {
    const float* src = (h == 0) ? inA : inB;
    for (int chunk = 0; chunk < 8; chunk++) {
      __syncthreads();  // previous chunk consumed
      // ---- stage B: 8 ic x 3 rows x 66 float4 (stride 264, idx = gx+4) ----
      for (int i = t; i < 8 * 3 * 66; i += 256) {
        int ic = i / 198, r = i - ic * 198;
        int rr = r / 66, q = r - rr * 66;
        int gy = y + rr - 1;
        uint32_t* dst = &Bst[(ic * 3 + rr) * BSTR + q * 4];
        uint4 u = make_uint4(0u, 0u, 0u, 0u);
        if ((unsigned)gy < 256u && q >= 1 && q <= 64) {
          const float* sp =
              src + ((size_t)(b * 64 + chunk * 8 + ic)) * HWc + (size_t)gy * 256;
          float4 v = *(const float4*)(sp + q * 4 - 4);  // gx = 4q-4..4q-1
          u.x = f2tf(v.x); u.y = f2tf(v.y); u.z = f2tf(v.z); u.w = f2tf(v.w);
        }
        *(uint4*)dst = u;
      }
      // ---- stage A: 64 m x 72 k (tap-major), hi/lo tf32 split ----
      const int icg0 = h * 64 + chunk * 8;
      for (int i = t; i < 64 * 72; i += 256) {
        int m = i / 72, k = i - m * 72;
        int tap = k >> 3, ic = k & 7;
        float v = 0.f;
        if (m < OCv) v = w[(size_t)(oc0 + m) * Ktot + (icg0 + ic) * 9 + tap];
        uint32_t hb = f2tf(v);
        Ah[m * ASTR + k] = hb;
        Al[m * ASTR + k] = f2tf(v - __uint_as_float(hb));
      }
      __syncthreads();

      if (wm * 32 < OCv) {  // warp has valid m rows
#pragma unroll
        for (int ks = 0; ks < 9; ks++) {
          const int ky = ks / 3, kx = ks % 3;  // compile-time after unroll
          const int rb0 = rB + ky * BSTR + kx + 3;
          const int rb1 = rb0 + 4 * 3 * BSTR;  // ic = tig+4
          uint32_t b0[8], b1[8];
#pragma unroll
          for (int j = 0; j < 8; j++) {
            b0[j] = Bst[rb0 + 8 * j];
            b1[j] = Bst[rb1 + 8 * j];
          }
#pragma unroll
          for (int f = 0; f < 2; f++) {
            if (wm * 32 + f * 16 >= OCv) break;
            const int ar = (wm * 32 + f * 16 + gid) * ASTR + ks * 8 + tig;
            uint32_t a0 = Ah[ar], a1 = Ah[ar + 8 * ASTR];
            uint32_t a2 = Ah[ar + 4], a3 = Ah[ar + 8 * ASTR + 4];
#pragma unroll
            for (int j = 0; j < 8; j++) mma8(acc[f][j], a0, a1, a2, a3, b0[j], b1[j]);
            a0 = Al[ar]; a1 = Al[ar + 8 * ASTR];
            a2 = Al[ar + 4]; a3 = Al[ar + 8 * ASTR + 4];
#pragma unroll
            for (int j = 0; j < 8; j++) mma8(acc[f][j], a0, a1, a2, a3, b0[j], b1[j]);
          }
        }
      }
    }
  }

  // ---- epilogue: bias, relu, residual; px = wn*64 + j*8 + tig*2 ----
#pragma unroll
  for (int f = 0; f < 2; f++) {
#pragma unroll
    for (int half = 0; half < 2; half++) {
      int m = wm * 32 + f * 16 + gid + half * 8;
      if (m >= OCv) continue;
      int oc = oc0 + m;
      float bv = bias[oc];
      size_t base =
          ((size_t)b * OC_total + oc) * HWc + (size_t)y * 256 + wn * 64 + tig * 2;
      float* op = out + base;
      const float* ap = addsrc ? addsrc + base : nullptr;
#pragma unroll
      for (int j = 0; j < 8; j++) {
        float v0 = acc[f][j][half * 2 + 0] + bv;
        float v1 = acc[f][j][half * 2 + 1] + bv;
        if (do_relu) { v0 = fmaxf(v0, 0.f); v1 = fmaxf(v1, 0.f); }
        if (ap) {
          float2 a2 = *(const float2*)(ap + j * 8);
          v0 += a2.x; v1 += a2.y;
        }
        *(float2*)(op + j * 8) = make_float2(v0, v1);
      }
    }
  }
}

// ---------------- deformable conv (G=8, Cg=8, K=3) ---------------------------
__global__ __launch_bounds__(256) void deform_kernel(
    const float* __restrict__ ref, const float* __restrict__ doff,
    const float* __restrict__ w_def, const float* __restrict__ b_def,
    float* __restrict__ out) {
  const int x = threadIdx.x, y = blockIdx.x, g = blockIdx.y, b = blockIdx.z;
  __shared__ float s_w[8][8][9];
  for (int i = threadIdx.x; i < 576; i += 256) {
    int o = i / 72, r = i - o * 72;
    s_w[o][0][r] = w_def[(g * 8 + o) * 72 + r];
  }
  __syncthreads();
  const float* refg = ref + (b * 64 + g * 8) * HWc;
  const float* offg = doff + (b * 144 + g * 18) * HWc + y * Wc + x;
  float acc[8];
#pragma unroll
  for (int o = 0; o < 8; o++) acc[o] = 0.f;
#pragma unroll 1
  for (int k = 0; k < 9; k++) {
    float dy = offg[(2 * k) * HWc];
    float dx = offg[(2 * k + 1) * HWc];
    float pyf = dy + (float)(y + k / 3 - 1);
    float pxf = dx + (float)(x + k % 3 - 1);
    float fy = floorf(pyf), fx = floorf(pxf);
    int y0 = (int)fy, x0 = (int)fx;
    float ly = pyf - fy, lx = pxf - fx;
    float w00 = (1.f - ly) * (1.f - lx), w01 = (1.f - ly) * lx;
    float w10 = ly * (1.f - lx), w11 = ly * lx;
    bool vy0 = (unsigned)y0 < 256u, vy1 = (unsigned)(y0 + 1) < 256u;
    bool vx0 = (unsigned)x0 < 256u, vx1 = (unsigned)(x0 + 1) < 256u;
    if (!(vy0 && vx0)) w00 = 0.f;
    if (!(vy0 && vx1)) w01 = 0.f;
    if (!(vy1 && vx0)) w10 = 0.f;
    if (!(vy1 && vx1)) w11 = 0.f;
    int cy0 = min(max(y0, 0), 255), cy1 = min(max(y0 + 1, 0), 255);
    int cx0 = min(max(x0, 0), 255), cx1 = min(max(x0 + 1, 0), 255);
    int i00 = cy0 * Wc + cx0, i01 = cy0 * Wc + cx1;
    int i10 = cy1 * Wc + cx0, i11 = cy1 * Wc + cx1;
#pragma unroll
    for (int cch = 0; cch < 8; cch++) {
      const float* rp = refg + cch * HWc;
      float s = w00 * rp[i00] + w01 * rp[i01] + w10 * rp[i10] + w11 * rp[i11];
#pragma unroll
      for (int o = 0; o < 8; o++) acc[o] = fmaf(s, s_w[o][cch][k], acc[o]);
    }
  }
#pragma unroll
  for (int o = 0; o < 8; o++)
    out[(b * 64 + g * 8 + o) * HWc + y * Wc + x] = acc[o] + b_def[g * 8 + o];
}

extern "C" void kernel_launch(void* const* d_in, const int* in_sizes, int n_in,
                              void* d_out, int out_size) {
  const float* offset = (const float*)d_in[0];
  const float* ref    = (const float*)d_in[1];
  const float* w_off  = (const float*)d_in[2];
  const float* b_off  = (const float*)d_in[3];
  const float* w_def  = (const float*)d_in[4];
  const float* b_def  = (const float*)d_in[5];
  const float* w_r1   = (const float*)d_in[6];
  const float* b_r1   = (const float*)d_in[7];
  const float* w_r2   = (const float*)d_in[8];
  const float* b_r2   = (const float*)d_in[9];
  float* out = (float*)d_out;

  float *p_doff, *p_aligned, *p_x1;
  cudaGetSymbolAddress((void**)&p_doff, g_doff);
  cudaGetSymbolAddress((void**)&p_aligned, g_aligned);
  cudaGetSymbolAddress((void**)&p_x1, g_x1);

  cudaFuncSetAttribute(conv3x3_mma<1>, cudaFuncAttributeMaxDynamicSharedMemorySize,
                       (int)SMEM_BYTES);
  cudaFuncSetAttribute(conv3x3_mma<2>, cudaFuncAttributeMaxDynamicSharedMemorySize,
                       (int)SMEM_BYTES);

  // 1) deform_offsets = conv3x3(offset)  64 -> 144 (oc blocks 64/64/16)
  conv3x3_mma<1><<<dim3(512, 3), 256, SMEM_BYTES>>>(offset, nullptr, w_off, b_off,
                                                    p_doff, nullptr, 144, 0);
  // 2) deformable conv
  deform_kernel<<<dim3(256, 8, 2), 256>>>(ref, p_doff, w_def, b_def, p_aligned);
  // 3) x1 = relu(conv3x3(concat(ref, aligned)))  128 -> 64
  conv3x3_mma<2><<<dim3(512, 1), 256, SMEM_BYTES>>>(ref, p_aligned, w_r1, b_r1,
                                                    p_x1, nullptr, 64, 1);
  // 4) out = relu(conv3x3(x1)) + aligned  64 -> 64
  conv3x3_mma<1><<<dim3(512, 1), 256, SMEM_BYTES>>>(p_x1, nullptr, w_r2, b_r2,
                                                    out, p_aligned, 64, 1);
}

// round 9
// speedup vs baseline: 3.3676x; 1.5556x over previous
#include <cuda_runtime.h>
#include <cuda_fp16.h>
#include <cstdint>

__device__ float g_doff[2 * 144 * 256 * 256];
__device__ float g_aligned[2 * 64 * 256 * 256];
__device__ float g_x1[2 * 64 * 256 * 256];

static constexpr int Hc = 256, Wc = 256, HWc = Hc * Wc;
static constexpr float WSCALE = 16.0f;
static constexpr float WINV = 1.0f / 16.0f;

// smem (uint32 words):
//  Bst: 8 channel-PAIRS x 3 rows x 264 (fp16x2: lo=ch even, hi=ch odd)
//  Ah/Al: 64 m x 84 (72 k-pairs in tap-major order: idx = tap*8 + pair)
static constexpr int BSTR = 264;
static constexpr int BST_U = 8 * 3 * BSTR;        // 6336
static constexpr int ASTR = 84;
static constexpr int AST_U = 64 * ASTR;           // 5376
static constexpr int SMEM_U = BST_U + 2 * AST_U;  // 17088
static constexpr size_t SMEM_BYTES = (size_t)SMEM_U * 4;

__device__ __forceinline__ uint32_t packh2(float lo, float hi) {
  __half2 h = __floats2half2_rn(lo, hi);  // .x = lo half
  return *reinterpret_cast<uint32_t*>(&h);
}
__device__ __forceinline__ void mma16(float* c, uint32_t a0, uint32_t a1,
                                      uint32_t a2, uint32_t a3, uint32_t b0,
                                      uint32_t b1) {
  asm volatile(
      "mma.sync.aligned.m16n8k16.row.col.f32.f16.f16.f32 "
      "{%0,%1,%2,%3}, {%4,%5,%6,%7}, {%8,%9}, {%0,%1,%2,%3};"
      : "+f"(c[0]), "+f"(c[1]), "+f"(c[2]), "+f"(c[3])
      : "r"(a0), "r"(a1), "r"(a2), "r"(a3), "r"(b0), "r"(b1));
}

// CTA: one full image row y (256 px) x 64 output channels.
// 8 warps: warp tile 32m x 64n. K chunked by 144 (16 ic x 9 taps, tap-major).
// fp16 path: B single-fp16 (10-bit mantissa == tf32), A hi/lo fp16, w scaled x16.
template <int NHALF>  // IC = NHALF*64
__global__ void __launch_bounds__(256, 2)
conv3x3_mma(const float* __restrict__ inA, const float* __restrict__ inB,
            const float* __restrict__ w, const float* __restrict__ bias,
            float* __restrict__ out, const float* __restrict__ addsrc,
            int OC_total, int do_relu) {
  extern __shared__ uint32_t smu[];
  uint32_t* Bst = smu;
  uint32_t* Ah = smu + BST_U;
  uint32_t* Al = Ah + AST_U;

  const int t = threadIdx.x, lane = t & 31, wid = t >> 5;
  const int gid = lane >> 2, tig = lane & 3;
  const int wm = wid & 1, wn = wid >> 1;

  const int y = blockIdx.x & 255, b = blockIdx.x >> 8;
  const int oc0 = blockIdx.y * 64;
  const int OCv = min(64, OC_total - oc0);
  const int Ktot = NHALF * 576;

  // B fragment base: pair = tig, rows = pair*3 + ky, col = px + kx + 3
  const int rB = tig * (3 * BSTR) + wn * 64 + gid;

  float acc[2][8][4];
#pragma unroll
  for (int f = 0; f < 2; f++)
#pragma unroll
    for (int j = 0; j < 8; j++)
#pragma unroll
      for (int e = 0; e < 4; e++) acc[f][j][e] = 0.f;

  for (int h = 0; h < NHALF; h++) {
    const float* src = (h == 0) ? inA : inB;
    for (int chunk = 0; chunk < 4; chunk++) {
      __syncthreads();  // previous chunk consumed
      const int icg0 = chunk * 16;
      // ---- stage B: 8 pairs x 3 rows x 66 word4 (fp16x2 of ch 2p / 2p+1) ----
      for (int i = t; i < 8 * 3 * 66; i += 256) {
        int p = i / 198, r = i - p * 198;
        int rr = r / 66, q = r - rr * 66;
        int gy = y + rr - 1;
        uint4 u = make_uint4(0u, 0u, 0u, 0u);
        if ((unsigned)gy < 256u && q >= 1 && q <= 64) {
          const float* sp0 =
              src + ((size_t)(b * 64 + icg0 + 2 * p)) * HWc + (size_t)gy * 256;
          const float* sp1 = sp0 + HWc;
          float4 v0 = *(const float4*)(sp0 + q * 4 - 4);
          float4 v1 = *(const float4*)(sp1 + q * 4 - 4);
          u.x = packh2(v0.x, v1.x);
          u.y = packh2(v0.y, v1.y);
          u.z = packh2(v0.z, v1.z);
          u.w = packh2(v0.w, v1.w);
        }
        *(uint4*)&Bst[(p * 3 + rr) * BSTR + q * 4] = u;
      }
      // ---- stage A: 64 m x 72 k-pairs (tap-major), hi/lo fp16, w x16 ----
      for (int i = t; i < 64 * 72; i += 256) {
        int m = i / 72, k = i - m * 72;
        int tap = k >> 3, p = k & 7;
        float w0 = 0.f, w1 = 0.f;
        if (m < OCv) {
          const float* wp = w + (size_t)(oc0 + m) * Ktot + (h * 64 + icg0) * 9;
          w0 = wp[(2 * p) * 9 + tap] * WSCALE;
          w1 = wp[(2 * p + 1) * 9 + tap] * WSCALE;
        }
        __half h0 = __float2half_rn(w0), h1 = __float2half_rn(w1);
        float l0 = w0 - __half2float(h0), l1 = w1 - __half2float(h1);
        __half2 hi2 = __halves2half2(h0, h1);
        Ah[m * ASTR + k] = *reinterpret_cast<uint32_t*>(&hi2);
        Al[m * ASTR + k] = packh2(l0, l1);
      }
      __syncthreads();

      if (wm * 32 < OCv) {
#pragma unroll
        for (int ks = 0; ks < 9; ks++) {
          const int ky = ks / 3, kx = ks % 3;  // compile-time after unroll
          const int rb0 = rB + ky * BSTR + kx + 3;
          const int rb1 = rb0 + 4 * 3 * BSTR;  // pair tig+4
          uint32_t b0[8], b1[8];
#pragma unroll
          for (int j = 0; j < 8; j++) {
            b0[j] = Bst[rb0 + 8 * j];
            b1[j] = Bst[rb1 + 8 * j];
          }
#pragma unroll
          for (int f = 0; f < 2; f++) {
            if (wm * 32 + f * 16 >= OCv) break;
            const int ar = (wm * 32 + f * 16 + gid) * ASTR + ks * 8 + tig;
            uint32_t a0 = Ah[ar], a1 = Ah[ar + 8 * ASTR];
            uint32_t a2 = Ah[ar + 4], a3 = Ah[ar + 8 * ASTR + 4];
#pragma unroll
            for (int j = 0; j < 8; j++) mma16(acc[f][j], a0, a1, a2, a3, b0[j], b1[j]);
            a0 = Al[ar]; a1 = Al[ar + 8 * ASTR];
            a2 = Al[ar + 4]; a3 = Al[ar + 8 * ASTR + 4];
#pragma unroll
            for (int j = 0; j < 8; j++) mma16(acc[f][j], a0, a1, a2, a3, b0[j], b1[j]);
          }
        }
      }
    }
  }

  // ---- epilogue: unscale, bias, relu, residual; px = wn*64 + j*8 + tig*2 ----
#pragma unroll
  for (int f = 0; f < 2; f++) {
#pragma unroll
    for (int half = 0; half < 2; half++) {
      int m = wm * 32 + f * 16 + gid + half * 8;
      if (m >= OCv) continue;
      int oc = oc0 + m;
      float bv = bias[oc];
      size_t base =
          ((size_t)b * OC_total + oc) * HWc + (size_t)y * 256 + wn * 64 + tig * 2;
      float* op = out + base;
      const float* ap = addsrc ? addsrc + base : nullptr;
#pragma unroll
      for (int j = 0; j < 8; j++) {
        float v0 = acc[f][j][half * 2 + 0] * WINV + bv;
        float v1 = acc[f][j][half * 2 + 1] * WINV + bv;
        if (do_relu) { v0 = fmaxf(v0, 0.f); v1 = fmaxf(v1, 0.f); }
        if (ap) {
          float2 a2 = *(const float2*)(ap + j * 8);
          v0 += a2.x; v1 += a2.y;
        }
        *(float2*)(op + j * 8) = make_float2(v0, v1);
      }
    }
  }
}

// ---------------- deformable conv (G=8, Cg=8, K=3) ---------------------------
__global__ __launch_bounds__(256) void deform_kernel(
    const float* __restrict__ ref, const float* __restrict__ doff,
    const float* __restrict__ w_def, const float* __restrict__ b_def,
    float* __restrict__ out) {
  const int x = threadIdx.x, y = blockIdx.x, g = blockIdx.y, b = blockIdx.z;
  __shared__ float s_w[8][8][9];
  for (int i = threadIdx.x; i < 576; i += 256) {
    int o = i / 72, r = i - o * 72;
    s_w[o][0][r] = w_def[(g * 8 + o) * 72 + r];
  }
  __syncthreads();
  const float* refg = ref + (b * 64 + g * 8) * HWc;
  const float* offg = doff + (b * 144 + g * 18) * HWc + y * Wc + x;
  float acc[8];
#pragma unroll
  for (int o = 0; o < 8; o++) acc[o] = 0.f;
#pragma unroll 1
  for (int k = 0; k < 9; k++) {
    float dy = offg[(2 * k) * HWc];
    float dx = offg[(2 * k + 1) * HWc];
    float pyf = dy + (float)(y + k / 3 - 1);
    float pxf = dx + (float)(x + k % 3 - 1);
    float fy = floorf(pyf), fx = floorf(pxf);
    int y0 = (int)fy, x0 = (int)fx;
    float ly = pyf - fy, lx = pxf - fx;
    float w00 = (1.f - ly) * (1.f - lx), w01 = (1.f - ly) * lx;
    float w10 = ly * (1.f - lx), w11 = ly * lx;
    bool vy0 = (unsigned)y0 < 256u, vy1 = (unsigned)(y0 + 1) < 256u;
    bool vx0 = (unsigned)x0 < 256u, vx1 = (unsigned)(x0 + 1) < 256u;
    if (!(vy0 && vx0)) w00 = 0.f;
    if (!(vy0 && vx1)) w01 = 0.f;
    if (!(vy1 && vx0)) w10 = 0.f;
    if (!(vy1 && vx1)) w11 = 0.f;
    int cy0 = min(max(y0, 0), 255), cy1 = min(max(y0 + 1, 0), 255);
    int cx0 = min(max(x0, 0), 255), cx1 = min(max(x0 + 1, 0), 255);
    int i00 = cy0 * Wc + cx0, i01 = cy0 * Wc + cx1;
    int i10 = cy1 * Wc + cx0, i11 = cy1 * Wc + cx1;
#pragma unroll
    for (int cch = 0; cch < 8; cch++) {
      const float* rp = refg + cch * HWc;
      float s = w00 * rp[i00] + w01 * rp[i01] + w10 * rp[i10] + w11 * rp[i11];
#pragma unroll
      for (int o = 0; o < 8; o++) acc[o] = fmaf(s, s_w[o][cch][k], acc[o]);
    }
  }
#pragma unroll
  for (int o = 0; o < 8; o++)
    out[(b * 64 + g * 8 + o) * HWc + y * Wc + x] = acc[o] + b_def[g * 8 + o];
}

extern "C" void kernel_launch(void* const* d_in, const int* in_sizes, int n_in,
                              void* d_out, int out_size) {
  const float* offset = (const float*)d_in[0];
  const float* ref    = (const float*)d_in[1];
  const float* w_off  = (const float*)d_in[2];
  const float* b_off  = (const float*)d_in[3];
  const float* w_def  = (const float*)d_in[4];
  const float* b_def  = (const float*)d_in[5];
  const float* w_r1   = (const float*)d_in[6];
  const float* b_r1   = (const float*)d_in[7];
  const float* w_r2   = (const float*)d_in[8];
  const float* b_r2   = (const float*)d_in[9];
  float* out = (float*)d_out;

  float *p_doff, *p_aligned, *p_x1;
  cudaGetSymbolAddress((void**)&p_doff, g_doff);
  cudaGetSymbolAddress((void**)&p_aligned, g_aligned);
  cudaGetSymbolAddress((void**)&p_x1, g_x1);

  cudaFuncSetAttribute(conv3x3_mma<1>, cudaFuncAttributeMaxDynamicSharedMemorySize,
                       (int)SMEM_BYTES);
  cudaFuncSetAttribute(conv3x3_mma<2>, cudaFuncAttributeMaxDynamicSharedMemorySize,
                       (int)SMEM_BYTES);

  // 1) deform_offsets = conv3x3(offset)  64 -> 144 (oc blocks 64/64/16)
  conv3x3_mma<1><<<dim3(512, 3), 256, SMEM_BYTES>>>(offset, nullptr, w_off, b_off,
                                                    p_doff, nullptr, 144, 0);
  // 2) deformable conv
  deform_kernel<<<dim3(256, 8, 2), 256>>>(ref, p_doff, w_def, b_def, p_aligned);
  // 3) x1 = relu(conv3x3(concat(ref, aligned)))  128 -> 64
  conv3x3_mma<2><<<dim3(512, 1), 256, SMEM_BYTES>>>(ref, p_aligned, w_r1, b_r1,
                                                    p_x1, nullptr, 64, 1);
  // 4) out = relu(conv3x3(x1)) + aligned  64 -> 64
  conv3x3_mma<1><<<dim3(512, 1), 256, SMEM_BYTES>>>(p_x1, nullptr, w_r2, b_r2,
                                                    out, p_aligned, 64, 1);
}